// round 12
// baseline (speedup 1.0000x reference)
#include <cuda_runtime.h>
#include <stdint.h>

#define NN 50000
#define EE 800000
#define EP (NN + EE)
#define DD 64
#define HH 4
#define CC 16
#define LL 3
#define CSRB 148
#define CSRT 1024
#define CHUNK 338      // ceil(NN / CSRB)

typedef unsigned long long ull;

// ---------------- scratch (device globals: no allocation allowed) ----------------
__device__ __align__(16) float g_h[NN * DD];
__device__ __align__(16) float g_h0[NN * DD];
__device__ __align__(16) float g_xl[NN * DD];
__device__ __align__(16) float g_xr[NN * DD];
__device__ __align__(16) float g_res[NN * DD];
__device__ int g_deg[NN];
__device__ int g_rowptr[NN + 1];
__device__ int g_rank[EE];
__device__ int g_col[EP];
__device__ int g_bsum[CSRB];
__device__ int g_barc;
__device__ int g_gen;

// ---------------- packed fp32x2 helpers (sm_100+ PTX) ----------------
__device__ __forceinline__ ull fma2(ull a, ull b, ull c) {
    ull d; asm("fma.rn.f32x2 %0, %1, %2, %3;" : "=l"(d) : "l"(a), "l"(b), "l"(c)); return d;
}
__device__ __forceinline__ ull add2(ull a, ull b) {
    ull d; asm("add.rn.f32x2 %0, %1, %2;" : "=l"(d) : "l"(a), "l"(b)); return d;
}
__device__ __forceinline__ ull mul2(ull a, ull b) {
    ull d; asm("mul.rn.f32x2 %0, %1, %2;" : "=l"(d) : "l"(a), "l"(b)); return d;
}
__device__ __forceinline__ ull abs2(ull a) { return a & 0x7FFFFFFF7FFFFFFFull; }
__device__ __forceinline__ ull splat2(float f) {
    ull d; asm("mov.b64 %0, {%1, %1};" : "=l"(d) : "f"(f)); return d;
}
union F4U { float4 f; ull u[2]; };

// ---------------- persistent CSR builder + fused input projection ----------------
__device__ __forceinline__ int bscan1024(int v, int* wsum) {
    int lane = threadIdx.x & 31, w = threadIdx.x >> 5;
    int s = v;
    #pragma unroll
    for (int o = 1; o < 32; o <<= 1) {
        int t = __shfl_up_sync(0xffffffffu, s, o);
        if (lane >= o) s += t;
    }
    if (lane == 31) wsum[w] = s;
    __syncthreads();
    if (w == 0) {
        int ws = wsum[lane];
        #pragma unroll
        for (int o = 1; o < 32; o <<= 1) {
            int t = __shfl_up_sync(0xffffffffu, ws, o);
            if (lane >= o) ws += t;
        }
        wsum[lane] = ws;
    }
    __syncthreads();
    return s + ((w > 0) ? wsum[w - 1] : 0);
}

__global__ __launch_bounds__(CSRT) void k_csr(
        const int* __restrict__ esrc, const int* __restrict__ edst,
        const float* __restrict__ x, const int* __restrict__ node_type,
        const float* __restrict__ Wt, const float* __restrict__ bt,
        const float* __restrict__ Et, const float* __restrict__ Wp,
        const float* __restrict__ bp) {
    __shared__ int wsum[32];
    __shared__ int s_bs[CSRB];
    __shared__ int s_gen;
    __shared__ float tmp[16][DD];
    int tid = threadIdx.x, b = blockIdx.x;
    const int stride = CSRB * CSRT;

    if (tid == 0) s_gen = atomicAdd(&g_gen, 0);
    __syncthreads();

#define GSYNC() do {                                                         \
        __syncthreads();                                                     \
        if (tid == 0) {                                                      \
            int tg = ++s_gen;                                                \
            __threadfence();                                                 \
            if (atomicAdd(&g_barc, 1) == CSRB - 1) {                         \
                atomicExch(&g_barc, 0);                                      \
                atomicExch(&g_gen, tg);                                      \
            } else {                                                         \
                while (atomicAdd(&g_gen, 0) < tg) { }                        \
            }                                                                \
        }                                                                    \
        __syncthreads();                                                     \
    } while (0)

    // phase A: degree init + input projection (independent work)
    for (int i = b * CSRT + tid; i < NN; i += stride) g_deg[i] = 0;
    {
        int nl = tid >> 6;                // node-local 0..15
        int c  = tid & 63;                // channel
        for (int nb = b * 16; nb < NN; nb += CSRB * 16) {
            int node = nb + nl;
            if (node < NN) {
                float a = bt[c];
                #pragma unroll
                for (int f = 0; f < 8; f++) a += x[node * 8 + f] * Wt[f * DD + c];
                tmp[nl][c] = fmaxf(a, 0.f);
            }
            __syncthreads();
            if (node < NN) {
                int t = node_type[node];
                float v = bp[c];
                #pragma unroll
                for (int k = 0; k < DD; k++) v += tmp[nl][k] * Wp[k * DD + c];
                #pragma unroll
                for (int j = 0; j < 16; j++) v += Et[t * 16 + j] * Wp[(DD + j) * DD + c];
                g_h[node * DD + c]  = v;
                g_h0[node * DD + c] = v;
            }
            __syncthreads();
        }
    }
    GSYNC();
    // phase B: count + record per-edge rank
    for (int i = b * CSRT + tid; i < EE; i += stride)
        g_rank[i] = atomicAdd(&g_deg[edst[i]], 1);
    GSYNC();
    // phase C: per-block inclusive scan of (deg + 1)  (+1 = self loop)
    int base = b * CHUNK;
    int n = NN - base; if (n > CHUNK) n = CHUNK;
    int idx = base + tid;
    int v = (tid < n) ? (g_deg[idx] + 1) : 0;
    int incl = bscan1024(v, wsum);
    if (tid == CSRT - 1) g_bsum[b] = incl;
    GSYNC();
    // phase D: scan block totals, write rowptr
    {
        int w2 = (tid < CSRB) ? g_bsum[tid] : 0;
        int incl2 = bscan1024(w2, wsum);
        if (tid < CSRB) s_bs[tid] = incl2;
        __syncthreads();
        int prefix = (b > 0) ? s_bs[b - 1] : 0;
        if (tid < n) g_rowptr[idx] = prefix + incl - v;
        if (b == 0 && tid == 0) g_rowptr[NN] = EP;
    }
    GSYNC();
    // phase E: atomic-free scatter (rank precomputed); self loop at last slot
    for (int i = b * CSRT + tid; i < EP; i += stride) {
        if (i < EE) {
            int d = edst[i];
            g_col[g_rowptr[d] + g_rank[i]] = esrc[i];
        } else {
            int nd = i - EE;
            g_col[g_rowptr[nd] + g_deg[nd]] = nd;
        }
    }
#undef GSYNC
}

// ---------------- fused 3x GEMM via column-pair FFMA2 ----------------
#define GTB 256
__global__ void __launch_bounds__(GTB) k_gemm3(
        const float* __restrict__ Wl, const float* __restrict__ bl,
        const float* __restrict__ Wr, const float* __restrict__ br,
        const float* __restrict__ Ws, const float* __restrict__ bs) {
    __shared__ float hs[64][DD];
    int base = blockIdx.x * 64;
    int t = threadIdx.x;
    for (int i = t; i < 64 * DD / 4; i += GTB) {
        int r = i >> 4, c4 = i & 15;
        int node = base + r;
        float4 v = (node < NN) ? *(const float4*)(g_h + node * DD + c4 * 4)
                               : make_float4(0.f, 0.f, 0.f, 0.f);
        *(float4*)&hs[r][c4 * 4] = v;
    }
    __syncthreads();
    int tc2 = t & 31;
    int tn  = t >> 5;
    const ull* WlP = (const ull*)Wl + tc2;
    const ull* WrP = (const ull*)Wr + tc2;
    const ull* WsP = (const ull*)Ws + tc2;
    ull aL[8] = {}, aR[8] = {}, aS[8] = {};
    #pragma unroll 4
    for (int k2 = 0; k2 < 32; k2++) {
        ull wl0 = WlP[(2 * k2) * 32], wl1 = WlP[(2 * k2 + 1) * 32];
        ull wr0 = WrP[(2 * k2) * 32], wr1 = WrP[(2 * k2 + 1) * 32];
        ull ws0 = WsP[(2 * k2) * 32], ws1 = WsP[(2 * k2 + 1) * 32];
        #pragma unroll
        for (int j = 0; j < 8; j++) {
            float2 hv = *(const float2*)&hs[tn + 8 * j][2 * k2];
            ull h2a = splat2(hv.x), h2b = splat2(hv.y);
            aL[j] = fma2(h2a, wl0, aL[j]); aL[j] = fma2(h2b, wl1, aL[j]);
            aR[j] = fma2(h2a, wr0, aR[j]); aR[j] = fma2(h2b, wr1, aR[j]);
            aS[j] = fma2(h2a, ws0, aS[j]); aS[j] = fma2(h2b, ws1, aS[j]);
        }
    }
    float2 bL = *(const float2*)&bl[2 * tc2];
    float2 bR = *(const float2*)&br[2 * tc2];
    float2 bS = *(const float2*)&bs[2 * tc2];
    #pragma unroll
    for (int j = 0; j < 8; j++) {
        int node = base + tn + 8 * j;
        if (node < NN) {
            float2 l = *(float2*)&aL[j]; l.x += bL.x; l.y += bL.y;
            *(float2*)(g_xl + node * DD + 2 * tc2) = l;
            float2 r = *(float2*)&aR[j]; r.x += bR.x; r.y += bR.y;
            *(float2*)(g_xr + node * DD + 2 * tc2) = r;
            float2 sv = *(float2*)&aS[j]; sv.x += bS.x; sv.y += bS.y;
            *(float2*)(g_res + node * DD + 2 * tc2) = sv;
        }
    }
}

// ---------------- GAT aggregation (coalesced rows, packed f32x2 edge math) ----------------
// leaky_relu(e, 0.2) == 0.6*e + 0.4*|e|  (exact identity for slope 0.2)
__device__ __forceinline__ float score2(ull xa, ull xb, ull ra, ull rb,
                                        ull aa, ull ab, ull C06, ull C04) {
    ull ea = add2(xa, ra), eb = add2(xb, rb);
    ull la = fma2(abs2(ea), C04, mul2(ea, C06));
    ull lb = fma2(abs2(eb), C04, mul2(eb, C06));
    ull tt = mul2(la, aa);
    tt = fma2(lb, ab, tt);
    float2 u = *(float2*)&tt;
    return u.x + u.y;
}

template <bool LAST>
__global__ void __launch_bounds__(256) k_gat(
        const float* __restrict__ att, const float* __restrict__ gamma,
        const float* __restrict__ beta, const float* __restrict__ alpha_p,
        const float* __restrict__ W1, const float* __restrict__ b1,
        const float* __restrict__ W2, const float* __restrict__ b2,
        float* __restrict__ out) {
    __shared__ float sout[8][DD];
    int gw = (blockIdx.x * blockDim.x + threadIdx.x) >> 5;
    if (gw >= NN) return;
    int lane = threadIdx.x & 31;
    int wib  = threadIdx.x >> 5;
    int node = gw;
    int eg   = lane >> 4;
    int hq   = lane & 15;
    const float NEG_INF = __int_as_float(0xff800000);
    const ull C06 = splat2(0.6f);
    const ull C04 = splat2(0.4f);

    F4U rU; rU.f = *(const float4*)(g_xr + node * DD + hq * 4);
    F4U aU; aU.f = *(const float4*)(att + hq * 4);
    ull ra = rU.u[0], rb = rU.u[1], aa = aU.u[0], ab = aU.u[1];

    float m = NEG_INF, s = 0.f;
    ull ca = 0ull, cb = 0ull;   // packed (0.f, 0.f)

    int beg = g_rowptr[node], end = g_rowptr[node + 1];
    for (int j = beg; j < end; j += 8) {
        int i0 = j + eg, i1 = j + 2 + eg, i2 = j + 4 + eg, i3 = j + 6 + eg;
        bool v0 = i0 < end, v1 = i1 < end, v2 = i2 < end, v3 = i3 < end;
        int s0 = v0 ? g_col[i0] : node;
        int s1 = v1 ? g_col[i1] : node;
        int s2 = v2 ? g_col[i2] : node;
        int s3 = v3 ? g_col[i3] : node;
        F4U x0, x1, x2, x3;
        x0.f = *(const float4*)(g_xl + s0 * DD + hq * 4);
        x1.f = *(const float4*)(g_xl + s1 * DD + hq * 4);
        x2.f = *(const float4*)(g_xl + s2 * DD + hq * 4);
        x3.f = *(const float4*)(g_xl + s3 * DD + hq * 4);
        float p0 = v0 ? score2(x0.u[0], x0.u[1], ra, rb, aa, ab, C06, C04) : NEG_INF;
        float p1 = v1 ? score2(x1.u[0], x1.u[1], ra, rb, aa, ab, C06, C04) : NEG_INF;
        float p2 = v2 ? score2(x2.u[0], x2.u[1], ra, rb, aa, ab, C06, C04) : NEG_INF;
        float p3 = v3 ? score2(x3.u[0], x3.u[1], ra, rb, aa, ab, C06, C04) : NEG_INF;
        // quad sums (full score on every lane of the head's quad group)
        p0 += __shfl_xor_sync(0xffffffffu, p0, 1); p0 += __shfl_xor_sync(0xffffffffu, p0, 2);
        p1 += __shfl_xor_sync(0xffffffffu, p1, 1); p1 += __shfl_xor_sync(0xffffffffu, p1, 2);
        p2 += __shfl_xor_sync(0xffffffffu, p2, 1); p2 += __shfl_xor_sync(0xffffffffu, p2, 2);
        p3 += __shfl_xor_sync(0xffffffffu, p3, 1); p3 += __shfl_xor_sync(0xffffffffu, p3, 2);
        // one max update per batch of 8 edges
        float lm = fmaxf(fmaxf(p0, p1), fmaxf(p2, p3));
        float bm = fmaxf(lm, __shfl_xor_sync(0xffffffffu, lm, 16));
        if (bm > m) {
            float f = __expf(m - bm);
            ull fv = splat2(f);
            s *= f; ca = mul2(ca, fv); cb = mul2(cb, fv);
            m = bm;
        }
        float w0 = __expf(p0 - m), w1 = __expf(p1 - m);
        float w2 = __expf(p2 - m), w3 = __expf(p3 - m);
        s += (w0 + w1) + (w2 + w3);
        ull wv;
        wv = splat2(w0); ca = fma2(wv, x0.u[0], ca); cb = fma2(wv, x0.u[1], cb);
        wv = splat2(w1); ca = fma2(wv, x1.u[0], ca); cb = fma2(wv, x1.u[1], cb);
        wv = splat2(w2); ca = fma2(wv, x2.u[0], ca); cb = fma2(wv, x2.u[1], cb);
        wv = splat2(w3); ca = fma2(wv, x3.u[0], ca); cb = fma2(wv, x3.u[1], cb);
    }
    F4U cf; cf.u[0] = ca; cf.u[1] = cb;
    float4 c = cf.f;
    s   += __shfl_xor_sync(0xffffffffu, s, 16);
    c.x += __shfl_xor_sync(0xffffffffu, c.x, 16);
    c.y += __shfl_xor_sync(0xffffffffu, c.y, 16);
    c.z += __shfl_xor_sync(0xffffffffu, c.z, 16);
    c.w += __shfl_xor_sync(0xffffffffu, c.w, 16);
    float inv = 1.f / (s + 1e-16f);

    if (eg == 0) {
        *(float4*)&sout[wib][hq * 4] =
            make_float4(c.x * inv, c.y * inv, c.z * inv, c.w * inv);
    }
    __syncwarp();

    float alpha = *alpha_p;
    int cch = lane * 2;
    float t0 = sout[wib][cch]     + g_res[node * DD + cch];
    float t1 = sout[wib][cch + 1] + g_res[node * DD + cch + 1];
    t0 = alpha * t0 + (1.f - alpha) * g_h0[node * DD + cch];
    t1 = alpha * t1 + (1.f - alpha) * g_h0[node * DD + cch + 1];
    float sum = t0 + t1;
    #pragma unroll
    for (int o = 1; o < 32; o <<= 1) sum += __shfl_xor_sync(0xffffffffu, sum, o);
    float mean = sum * (1.f / 64.f);
    float d0 = t0 - mean, d1 = t1 - mean;
    float vs = d0 * d0 + d1 * d1;
    #pragma unroll
    for (int o = 1; o < 32; o <<= 1) vs += __shfl_xor_sync(0xffffffffu, vs, o);
    float rstd = rsqrtf(vs * (1.f / 64.f) + 1e-5f);
    float h0v = gamma[cch]     * d0 * rstd + beta[cch];
    float h1v = gamma[cch + 1] * d1 * rstd + beta[cch + 1];

    if (!LAST) {
        g_h[node * DD + cch]     = h0v;
        g_h[node * DD + cch + 1] = h1v;
    } else {
        sout[wib][cch]     = h0v;
        sout[wib][cch + 1] = h1v;
        __syncwarp();
        float z = b1[lane];
        #pragma unroll
        for (int k = 0; k < DD; k++) z += sout[wib][k] * W1[k * 32 + lane];
        z = fmaxf(z, 0.f);
        float ps = z * W2[lane];
        #pragma unroll
        for (int o = 1; o < 32; o <<= 1) ps += __shfl_xor_sync(0xffffffffu, ps, o);
        if (lane == 0) out[node] = 1.f / (1.f + __expf(-(ps + b2[0])));
    }
}

// ---------------- launch ----------------
extern "C" void kernel_launch(void* const* d_in, const int* in_sizes, int n_in,
                              void* d_out, int out_size) {
    const float* x         = (const float*)d_in[0];
    const int*   node_type = (const int*)d_in[1];
    const int*   esrc      = (const int*)d_in[2];
    const int*   edst      = (const int*)d_in[3];
    const float* Wt        = (const float*)d_in[4];
    const float* bt        = (const float*)d_in[5];
    const float* Et        = (const float*)d_in[6];
    const float* Wp        = (const float*)d_in[7];
    const float* bp        = (const float*)d_in[8];
    const float* Wl        = (const float*)d_in[9];
    const float* bl        = (const float*)d_in[10];
    const float* Wr        = (const float*)d_in[11];
    const float* br        = (const float*)d_in[12];
    const float* att       = (const float*)d_in[13];
    const float* Wres      = (const float*)d_in[14];
    const float* bconv     = (const float*)d_in[15];
    const float* gamma     = (const float*)d_in[16];
    const float* beta      = (const float*)d_in[17];
    const float* alpha     = (const float*)d_in[18];
    const float* W1        = (const float*)d_in[19];
    const float* b1        = (const float*)d_in[20];
    const float* W2        = (const float*)d_in[21];
    const float* b2        = (const float*)d_in[22];
    float* out = (float*)d_out;

    // launch #5 under ncu (-s 5) = k_gemm3 layer 3
    k_csr<<<CSRB, CSRT>>>(esrc, edst, x, node_type, Wt, bt, Et, Wp, bp);  // 0

    for (int l = 0; l < LL; l++) {
        k_gemm3<<<(NN + 63) / 64, GTB>>>(Wl + l * DD * DD, bl + l * DD,   // 1,3,5
                                         Wr + l * DD * DD, br + l * DD,
                                         Wres + l * DD * DD, bconv + l * DD);
        if (l < LL - 1)
            k_gat<false><<<(NN + 7) / 8, 256>>>(att + l * HH * CC,        // 2,4
                gamma + l * DD, beta + l * DD, alpha,
                nullptr, nullptr, nullptr, nullptr, nullptr);
        else
            k_gat<true><<<(NN + 7) / 8, 256>>>(att + l * HH * CC,         // 6
                gamma + l * DD, beta + l * DD, alpha,
                W1, b1, W2, b2, out);
    }
}

// round 13
// speedup vs baseline: 1.0794x; 1.0794x over previous
#include <cuda_runtime.h>
#include <stdint.h>

#define NN 50000
#define EE 800000
#define EP (NN + EE)
#define DD 64
#define HH 4
#define CC 16
#define LL 3
#define CSRB 148
#define CSRT 1024
#define CHUNK 338      // ceil(NN / CSRB)

typedef unsigned long long ull;

// ---------------- scratch (device globals: no allocation allowed) ----------------
__device__ __align__(16) float g_h[NN * DD];
__device__ __align__(16) float g_h0[NN * DD];
__device__ __align__(16) float g_xl[NN * DD];
__device__ __align__(16) float g_xr[NN * DD];
__device__ __align__(16) float g_res[NN * DD];
__device__ int g_deg[NN];
__device__ int g_rowptr[NN + 1];
__device__ int g_cursor[NN];
__device__ int g_col[EP];
__device__ int g_bsum[CSRB];
__device__ int g_barc;
__device__ int g_gen;

// ---------------- packed fp32x2 helpers (sm_100+ PTX; add/mul/fma only) ----------------
__device__ __forceinline__ ull fma2(ull a, ull b, ull c) {
    ull d; asm("fma.rn.f32x2 %0, %1, %2, %3;" : "=l"(d) : "l"(a), "l"(b), "l"(c)); return d;
}
__device__ __forceinline__ ull add2(ull a, ull b) {
    ull d; asm("add.rn.f32x2 %0, %1, %2;" : "=l"(d) : "l"(a), "l"(b)); return d;
}
__device__ __forceinline__ ull mul2(ull a, ull b) {
    ull d; asm("mul.rn.f32x2 %0, %1, %2;" : "=l"(d) : "l"(a), "l"(b)); return d;
}
__device__ __forceinline__ ull abs2(ull a) { return a & 0x7FFFFFFF7FFFFFFFull; }
__device__ __forceinline__ ull splat2(float f) {
    ull d; asm("mov.b64 %0, {%1, %1};" : "=l"(d) : "f"(f)); return d;
}
union F4U { float4 f; ull u[2]; };

// ---------------- persistent CSR builder (R10 version) ----------------
__device__ __forceinline__ int bscan1024(int v, int* wsum) {
    int lane = threadIdx.x & 31, w = threadIdx.x >> 5;
    int s = v;
    #pragma unroll
    for (int o = 1; o < 32; o <<= 1) {
        int t = __shfl_up_sync(0xffffffffu, s, o);
        if (lane >= o) s += t;
    }
    if (lane == 31) wsum[w] = s;
    __syncthreads();
    if (w == 0) {
        int ws = wsum[lane];
        #pragma unroll
        for (int o = 1; o < 32; o <<= 1) {
            int t = __shfl_up_sync(0xffffffffu, ws, o);
            if (lane >= o) ws += t;
        }
        wsum[lane] = ws;
    }
    __syncthreads();
    return s + ((w > 0) ? wsum[w - 1] : 0);
}

__global__ __launch_bounds__(CSRT) void k_csr(const int* __restrict__ esrc,
                                              const int* __restrict__ edst) {
    __shared__ int wsum[32];
    __shared__ int s_bs[CSRB];
    __shared__ int s_gen;
    int tid = threadIdx.x, b = blockIdx.x;
    const int stride = CSRB * CSRT;

    if (tid == 0) s_gen = atomicAdd(&g_gen, 0);
    __syncthreads();

#define GSYNC() do {                                                         \
        __syncthreads();                                                     \
        if (tid == 0) {                                                      \
            int tg = ++s_gen;                                                \
            __threadfence();                                                 \
            if (atomicAdd(&g_barc, 1) == CSRB - 1) {                         \
                atomicExch(&g_barc, 0);                                      \
                atomicExch(&g_gen, tg);                                      \
            } else {                                                         \
                while (atomicAdd(&g_gen, 0) < tg) { }                        \
            }                                                                \
        }                                                                    \
        __syncthreads();                                                     \
    } while (0)

    for (int i = b * CSRT + tid; i < NN; i += stride) g_deg[i] = 1;
    GSYNC();
    for (int i = b * CSRT + tid; i < EE; i += stride) atomicAdd(&g_deg[edst[i]], 1);
    GSYNC();
    int base = b * CHUNK;
    int n = NN - base; if (n > CHUNK) n = CHUNK;
    int idx = base + tid;
    int v = (tid < n) ? g_deg[idx] : 0;
    int incl = bscan1024(v, wsum);
    if (tid == CSRT - 1) g_bsum[b] = incl;
    GSYNC();
    {
        int w2 = (tid < CSRB) ? g_bsum[tid] : 0;
        int incl2 = bscan1024(w2, wsum);
        if (tid < CSRB) s_bs[tid] = incl2;
        __syncthreads();
        int prefix = (b > 0) ? s_bs[b - 1] : 0;
        if (tid < n) {
            int ex = prefix + incl - v;
            g_rowptr[idx] = ex;
            g_cursor[idx] = ex;
        }
        if (b == 0 && tid == 0) g_rowptr[NN] = EP;
    }
    GSYNC();
    for (int i = b * CSRT + tid; i < EP; i += stride) {
        if (i < EE) {
            int pos = atomicAdd(&g_cursor[edst[i]], 1);
            g_col[pos] = esrc[i];
        } else {
            int nd = i - EE;
            int pos = atomicAdd(&g_cursor[nd], 1);
            g_col[pos] = nd;
        }
    }
#undef GSYNC
}

// ---------------- input projection ----------------
__global__ void k_input(const float* __restrict__ x, const int* __restrict__ node_type,
                        const float* __restrict__ Wt, const float* __restrict__ bt,
                        const float* __restrict__ Et, const float* __restrict__ Wp,
                        const float* __restrict__ bp) {
    __shared__ float tmp[4][DD];
    int nl = threadIdx.x >> 6;
    int c  = threadIdx.x & 63;
    int node = blockIdx.x * 4 + nl;
    float a = 0.f;
    if (node < NN) {
        a = bt[c];
        #pragma unroll
        for (int f = 0; f < 8; f++) a += x[node * 8 + f] * Wt[f * DD + c];
        tmp[nl][c] = fmaxf(a, 0.f);
    }
    __syncthreads();
    if (node < NN) {
        int t = node_type[node];
        float b = bp[c];
        #pragma unroll
        for (int k = 0; k < DD; k++) b += tmp[nl][k] * Wp[k * DD + c];
        #pragma unroll
        for (int j = 0; j < 16; j++) b += Et[t * 16 + j] * Wp[(DD + j) * DD + c];
        g_h[node * DD + c]  = b;
        g_h0[node * DD + c] = b;
    }
}

// ---------------- fused 3x GEMM (R10 scalar version — proven) ----------------
#define GTB 256
__global__ void __launch_bounds__(GTB) k_gemm3(
        const float* __restrict__ Wl, const float* __restrict__ bl,
        const float* __restrict__ Wr, const float* __restrict__ br,
        const float* __restrict__ Ws, const float* __restrict__ bs) {
    __shared__ float hs[32][DD];
    int base = blockIdx.x * 32;
    int t = threadIdx.x;
    for (int i = t; i < 32 * DD; i += GTB) {
        int r = i >> 6, c = i & 63;
        int node = base + r;
        hs[r][c] = (node < NN) ? g_h[node * DD + c] : 0.f;
    }
    __syncthreads();
    int tc = t & 63;
    int tn = t >> 6;
    float aL[8] = {}, aR[8] = {}, aS[8] = {};
    #pragma unroll 8
    for (int k = 0; k < DD; k++) {
        float wl = Wl[k * DD + tc], wr = Wr[k * DD + tc], ws = Ws[k * DD + tc];
        #pragma unroll
        for (int j = 0; j < 8; j++) {
            float hv = hs[tn + 4 * j][k];
            aL[j] += hv * wl; aR[j] += hv * wr; aS[j] += hv * ws;
        }
    }
    float bL = bl[tc], bR = br[tc], bS = bs[tc];
    #pragma unroll
    for (int j = 0; j < 8; j++) {
        int node = base + tn + 4 * j;
        if (node < NN) {
            g_xl[node * DD + tc]  = aL[j] + bL;
            g_xr[node * DD + tc]  = aR[j] + bR;
            g_res[node * DD + tc] = aS[j] + bS;
        }
    }
}

// ---------------- GAT aggregation (coalesced rows, packed f32x2 edge math) ----------------
// leaky_relu(e, 0.2) == 0.6*e + 0.4*|e|  (exact identity for slope 0.2)
__device__ __forceinline__ float score2(ull xa, ull xb, ull ra, ull rb,
                                        ull aa, ull ab, ull C06, ull C04) {
    ull ea = add2(xa, ra), eb = add2(xb, rb);
    ull la = fma2(abs2(ea), C04, mul2(ea, C06));
    ull lb = fma2(abs2(eb), C04, mul2(eb, C06));
    ull tt = mul2(la, aa);
    tt = fma2(lb, ab, tt);
    float2 u = *(float2*)&tt;
    return u.x + u.y;
}

template <bool LAST>
__global__ void __launch_bounds__(256) k_gat(
        const float* __restrict__ att, const float* __restrict__ gamma,
        const float* __restrict__ beta, const float* __restrict__ alpha_p,
        const float* __restrict__ W1, const float* __restrict__ b1,
        const float* __restrict__ W2, const float* __restrict__ b2,
        float* __restrict__ out) {
    __shared__ float sout[8][DD];
    int gw = (blockIdx.x * blockDim.x + threadIdx.x) >> 5;
    if (gw >= NN) return;
    int lane = threadIdx.x & 31;
    int wib  = threadIdx.x >> 5;
    int node = gw;
    int eg   = lane >> 4;
    int hq   = lane & 15;
    const float NEG_INF = __int_as_float(0xff800000);
    const ull C06 = splat2(0.6f);
    const ull C04 = splat2(0.4f);

    F4U rU; rU.f = *(const float4*)(g_xr + node * DD + hq * 4);
    F4U aU; aU.f = *(const float4*)(att + hq * 4);
    ull ra = rU.u[0], rb = rU.u[1], aa = aU.u[0], ab = aU.u[1];

    float m = NEG_INF, s = 0.f;
    ull ca = 0ull, cb = 0ull;   // packed (0.f, 0.f)

    int beg = g_rowptr[node], end = g_rowptr[node + 1];
    for (int j = beg; j < end; j += 8) {
        int i0 = j + eg, i1 = j + 2 + eg, i2 = j + 4 + eg, i3 = j + 6 + eg;
        bool v0 = i0 < end, v1 = i1 < end, v2 = i2 < end, v3 = i3 < end;
        int s0 = v0 ? g_col[i0] : node;
        int s1 = v1 ? g_col[i1] : node;
        int s2 = v2 ? g_col[i2] : node;
        int s3 = v3 ? g_col[i3] : node;
        F4U x0, x1, x2, x3;
        x0.f = *(const float4*)(g_xl + s0 * DD + hq * 4);
        x1.f = *(const float4*)(g_xl + s1 * DD + hq * 4);
        x2.f = *(const float4*)(g_xl + s2 * DD + hq * 4);
        x3.f = *(const float4*)(g_xl + s3 * DD + hq * 4);
        float p0 = v0 ? score2(x0.u[0], x0.u[1], ra, rb, aa, ab, C06, C04) : NEG_INF;
        float p1 = v1 ? score2(x1.u[0], x1.u[1], ra, rb, aa, ab, C06, C04) : NEG_INF;
        float p2 = v2 ? score2(x2.u[0], x2.u[1], ra, rb, aa, ab, C06, C04) : NEG_INF;
        float p3 = v3 ? score2(x3.u[0], x3.u[1], ra, rb, aa, ab, C06, C04) : NEG_INF;
        // quad sums (full score on every lane of the head's quad group)
        p0 += __shfl_xor_sync(0xffffffffu, p0, 1); p0 += __shfl_xor_sync(0xffffffffu, p0, 2);
        p1 += __shfl_xor_sync(0xffffffffu, p1, 1); p1 += __shfl_xor_sync(0xffffffffu, p1, 2);
        p2 += __shfl_xor_sync(0xffffffffu, p2, 1); p2 += __shfl_xor_sync(0xffffffffu, p2, 2);
        p3 += __shfl_xor_sync(0xffffffffu, p3, 1); p3 += __shfl_xor_sync(0xffffffffu, p3, 2);
        // one max update per batch of 8 edges
        float lm = fmaxf(fmaxf(p0, p1), fmaxf(p2, p3));
        float bm = fmaxf(lm, __shfl_xor_sync(0xffffffffu, lm, 16));
        if (bm > m) {
            float f = __expf(m - bm);
            ull fv = splat2(f);
            s *= f; ca = mul2(ca, fv); cb = mul2(cb, fv);
            m = bm;
        }
        float w0 = __expf(p0 - m), w1 = __expf(p1 - m);
        float w2 = __expf(p2 - m), w3 = __expf(p3 - m);
        s += (w0 + w1) + (w2 + w3);
        ull wv;
        wv = splat2(w0); ca = fma2(wv, x0.u[0], ca); cb = fma2(wv, x0.u[1], cb);
        wv = splat2(w1); ca = fma2(wv, x1.u[0], ca); cb = fma2(wv, x1.u[1], cb);
        wv = splat2(w2); ca = fma2(wv, x2.u[0], ca); cb = fma2(wv, x2.u[1], cb);
        wv = splat2(w3); ca = fma2(wv, x3.u[0], ca); cb = fma2(wv, x3.u[1], cb);
    }
    F4U cf; cf.u[0] = ca; cf.u[1] = cb;
    float4 c = cf.f;
    s   += __shfl_xor_sync(0xffffffffu, s, 16);
    c.x += __shfl_xor_sync(0xffffffffu, c.x, 16);
    c.y += __shfl_xor_sync(0xffffffffu, c.y, 16);
    c.z += __shfl_xor_sync(0xffffffffu, c.z, 16);
    c.w += __shfl_xor_sync(0xffffffffu, c.w, 16);
    float inv = 1.f / (s + 1e-16f);

    if (eg == 0) {
        *(float4*)&sout[wib][hq * 4] =
            make_float4(c.x * inv, c.y * inv, c.z * inv, c.w * inv);
    }
    __syncwarp();

    float alpha = *alpha_p;
    int cch = lane * 2;
    float t0 = sout[wib][cch]     + g_res[node * DD + cch];
    float t1 = sout[wib][cch + 1] + g_res[node * DD + cch + 1];
    t0 = alpha * t0 + (1.f - alpha) * g_h0[node * DD + cch];
    t1 = alpha * t1 + (1.f - alpha) * g_h0[node * DD + cch + 1];
    float sum = t0 + t1;
    #pragma unroll
    for (int o = 1; o < 32; o <<= 1) sum += __shfl_xor_sync(0xffffffffu, sum, o);
    float mean = sum * (1.f / 64.f);
    float d0 = t0 - mean, d1 = t1 - mean;
    float vs = d0 * d0 + d1 * d1;
    #pragma unroll
    for (int o = 1; o < 32; o <<= 1) vs += __shfl_xor_sync(0xffffffffu, vs, o);
    float rstd = rsqrtf(vs * (1.f / 64.f) + 1e-5f);
    float h0v = gamma[cch]     * d0 * rstd + beta[cch];
    float h1v = gamma[cch + 1] * d1 * rstd + beta[cch + 1];

    if (!LAST) {
        g_h[node * DD + cch]     = h0v;
        g_h[node * DD + cch + 1] = h1v;
    } else {
        sout[wib][cch]     = h0v;
        sout[wib][cch + 1] = h1v;
        __syncwarp();
        float z = b1[lane];
        #pragma unroll
        for (int k = 0; k < DD; k++) z += sout[wib][k] * W1[k * 32 + lane];
        z = fmaxf(z, 0.f);
        float ps = z * W2[lane];
        #pragma unroll
        for (int o = 1; o < 32; o <<= 1) ps += __shfl_xor_sync(0xffffffffu, ps, o);
        if (lane == 0) out[node] = 1.f / (1.f + __expf(-(ps + b2[0])));
    }
}

// ---------------- launch ----------------
extern "C" void kernel_launch(void* const* d_in, const int* in_sizes, int n_in,
                              void* d_out, int out_size) {
    const float* x         = (const float*)d_in[0];
    const int*   node_type = (const int*)d_in[1];
    const int*   esrc      = (const int*)d_in[2];
    const int*   edst      = (const int*)d_in[3];
    const float* Wt        = (const float*)d_in[4];
    const float* bt        = (const float*)d_in[5];
    const float* Et        = (const float*)d_in[6];
    const float* Wp        = (const float*)d_in[7];
    const float* bp        = (const float*)d_in[8];
    const float* Wl        = (const float*)d_in[9];
    const float* bl        = (const float*)d_in[10];
    const float* Wr        = (const float*)d_in[11];
    const float* br        = (const float*)d_in[12];
    const float* att       = (const float*)d_in[13];
    const float* Wres      = (const float*)d_in[14];
    const float* bconv     = (const float*)d_in[15];
    const float* gamma     = (const float*)d_in[16];
    const float* beta      = (const float*)d_in[17];
    const float* alpha     = (const float*)d_in[18];
    const float* W1        = (const float*)d_in[19];
    const float* b1        = (const float*)d_in[20];
    const float* W2        = (const float*)d_in[21];
    const float* b2        = (const float*)d_in[22];
    float* out = (float*)d_out;

    // launch #5 under ncu (-s 5) = k_gat layer 2
    k_csr<<<CSRB, CSRT>>>(esrc, edst);                                   // 0
    k_input<<<(NN + 3) / 4, 256>>>(x, node_type, Wt, bt, Et, Wp, bp);    // 1

    for (int l = 0; l < LL; l++) {
        k_gemm3<<<(NN + 31) / 32, GTB>>>(Wl + l * DD * DD, bl + l * DD,  // 2,4,6
                                         Wr + l * DD * DD, br + l * DD,
                                         Wres + l * DD * DD, bconv + l * DD);
        if (l < LL - 1)
            k_gat<false><<<(NN + 7) / 8, 256>>>(att + l * HH * CC,       // 3,5
                gamma + l * DD, beta + l * DD, alpha,
                nullptr, nullptr, nullptr, nullptr, nullptr);
        else
            k_gat<true><<<(NN + 7) / 8, 256>>>(att + l * HH * CC,       // 7
                gamma + l * DD, beta + l * DD, alpha,
                W1, b1, W2, b2, out);
    }
}